// round 11
// baseline (speedup 1.0000x reference)
#include <cuda_runtime.h>

#define GS      20
#define PARAM   40
#define NN      (GS * PARAM)     // 800
#define NSYS    80               // B*A
#define MST     44               // padded matrix stride
#define NITER   3                // sweeps; trunc <= ||K||^4 ~ 4e-4 worst case

// ---------------------------------------------------------------------------
// One CTA per system, 800 threads.
// P = I(x)S + M(x)Ng,  F = S/2 - I,  G = F^2.
// Bpre = 0.5(I-F)(I+G+G^2): Bpre*S = I - F^6 (bias 1.5e-5, measured).
// Powers of F commute, so C = Bpre*Ng = 0.5(I+G+G^2)(I-F)Ng:
//   P1: G = F*F (warps 0-9)  ||  D = Ng - F*Ng (warps 10-19)
//   P2: R = G*D (warps 0-9)  ||  e = (I(x)G)v (threads >=320)
//   P3: C = 0.5(D+R+G*R)     ||  f = (I(x)G)e, u = v+e+f
//   P4: b = 0.5(u - (I(x)F)u) = (I(x)Bpre)v ; x0 = b
// Then 3 Richardson sweeps x <- b - (M(x)C)x, clip, store.
// ---------------------------------------------------------------------------

#define GM_PLAIN 0   // out = acc
#define GM_DNEG  1   // out = B[r,c] - acc           (D = Ng - F*Ng)
#define GM_CFIN  2   // out = 0.5*(E[r,c]+B[r,c]+acc) (C = 0.5(D + R + G*R))

// Warp-cooperative 40x40 GEMM, 10 warps (vt in [0,320)).
// Warp w: rows 4w..4w+3. lane: rr=lane>>4 -> row pair (4w+2rr, +1), cc=lane&15.
// Cols: pair {2cc,2cc+1}; cc<4 additionally {2cc+32,2cc+33}. rr=0/1 halves read
// the SAME B addresses -> broadcast dedup: 160 unique B bytes per warp per k.
template <int MODE>
__device__ __forceinline__ void gemm40x(float* __restrict__ D,
                                        const float* __restrict__ A,
                                        const float* __restrict__ B,
                                        const float* __restrict__ E,
                                        int vt)
{
    const int lane = vt & 31;
    const int w    = vt >> 5;        // 0..9
    const int rr   = lane >> 4;      // 0..1
    const int cc   = lane & 15;      // 0..15
    const int r0   = 4 * w + 2 * rr;
    const int r1   = r0 + 1;
    const int c0   = 2 * cc;         // 0..30
    const int c1   = 2 * cc + 32;    // 32..38 valid when cc<4
    const bool has2 = (cc < 4);

    float a00 = 0.f, a01 = 0.f, a10 = 0.f, a11 = 0.f;
    float b00 = 0.f, b01 = 0.f, b10 = 0.f, b11 = 0.f;
    const float4* A0 = (const float4*)(A + r0 * MST);
    const float4* A1 = (const float4*)(A + r1 * MST);
    #pragma unroll
    for (int k4 = 0; k4 < 10; ++k4) {
        float4 av0 = A0[k4];
        float4 av1 = A1[k4];
        #pragma unroll
        for (int j = 0; j < 4; ++j) {
            float x0 = (j == 0) ? av0.x : (j == 1) ? av0.y : (j == 2) ? av0.z : av0.w;
            float x1 = (j == 0) ? av1.x : (j == 1) ? av1.y : (j == 2) ? av1.z : av1.w;
            const float* Bk = B + (4 * k4 + j) * MST;
            float2 bb = *(const float2*)(Bk + c0);
            a00 = fmaf(x0, bb.x, a00);  a01 = fmaf(x0, bb.y, a01);
            a10 = fmaf(x1, bb.x, a10);  a11 = fmaf(x1, bb.y, a11);
            if (has2) {
                float2 bc = *(const float2*)(Bk + c1);
                b00 = fmaf(x0, bc.x, b00);  b01 = fmaf(x0, bc.y, b01);
                b10 = fmaf(x1, bc.x, b10);  b11 = fmaf(x1, bc.y, b11);
            }
        }
    }
    // epilogue + float2 stores
    #pragma unroll
    for (int s = 0; s < 4; ++s) {
        if ((s >= 2) && !has2) break;
        int   r  = (s & 1) ? r1 : r0;
        int   c  = (s < 2) ? c0 : c1;
        float v0 = (s == 0) ? a00 : (s == 1) ? a10 : (s == 2) ? b00 : b10;
        float v1 = (s == 0) ? a01 : (s == 1) ? a11 : (s == 2) ? b01 : b11;
        float2 o;
        if (MODE == GM_DNEG) {
            o.x = B[r * MST + c]     - v0;
            o.y = B[r * MST + c + 1] - v1;
        } else if (MODE == GM_CFIN) {
            o.x = 0.5f * (E[r * MST + c]     + B[r * MST + c]     + v0);
            o.y = 0.5f * (E[r * MST + c + 1] + B[r * MST + c + 1] + v1);
        } else {
            o.x = v0; o.y = v1;
        }
        *(float2*)(D + r * MST + c) = o;
    }
}

// dot(Mat[p,:], vec[g,:]) with float4 reads (stride-MST matrix, stride-40 vec)
__device__ __forceinline__ float rowdot40(const float* __restrict__ Mrow,
                                          const float* __restrict__ vrow)
{
    const float4* m4 = (const float4*)Mrow;
    const float4* v4 = (const float4*)vrow;
    float acc = 0.f;
    #pragma unroll
    for (int i = 0; i < 10; ++i) {
        float4 m = m4[i], v = v4[i];
        acc = fmaf(m.x, v.x, acc);
        acc = fmaf(m.y, v.y, acc);
        acc = fmaf(m.z, v.z, acc);
        acc = fmaf(m.w, v.w, acc);
    }
    return acc;
}

__global__ __launch_bounds__(NN, 1)
void gliam_fused_kernel(const float* __restrict__ mat,        // (80,20,20)
                        const float* __restrict__ val,        // (80,800)
                        const float* __restrict__ selfintact, // (40,40)
                        const float* __restrict__ neigintact, // (40,40)
                        float* __restrict__ out)              // (80,800)
{
    __shared__ __align__(16) float mF [PARAM * MST];  // F = S/2 - I
    __shared__ __align__(16) float mNg[PARAM * MST];  // Ng
    __shared__ __align__(16) float mG [PARAM * MST];  // G = F^2
    __shared__ __align__(16) float mD [PARAM * MST];  // D = (I-F)Ng
    __shared__ __align__(16) float mR [PARAM * MST];  // R = G*D
    __shared__ __align__(16) float mC [PARAM * MST];  // C
    __shared__ __align__(16) float sV [NN];           // v
    __shared__ __align__(16) float sE [NN];           // e = (I(x)G)v
    __shared__ __align__(16) float sx [NN];           // iterate
    __shared__ __align__(16) float sT [NN];           // u, then sweep scratch
    __shared__ __align__(16) float sM [GS * GS];      // M

    const int sys = blockIdx.x;
    const int t   = threadIdx.x;     // 0..799
    const int g   = t / PARAM;       // 0..19
    const int p   = t % PARAM;       // 0..39

    // ---- stage inputs ----
    {
        int i0 = t, i1 = t + NN;
        int r0 = i0 / PARAM, c0 = i0 % PARAM;
        int r1 = i1 / PARAM, c1 = i1 % PARAM;
        mF [r0 * MST + c0] = 0.5f * selfintact[i0] - (r0 == c0 ? 1.0f : 0.0f);
        mF [r1 * MST + c1] = 0.5f * selfintact[i1] - (r1 == c1 ? 1.0f : 0.0f);
        mNg[r0 * MST + c0] = neigintact[i0];
        mNg[r1 * MST + c1] = neigintact[i1];
        sV[t] = val[sys * NN + t];
        if (t < GS * GS) sM[t] = mat[sys * GS * GS + t];
    }
    __syncthreads();

    // ---- P1: G = F*F  ||  D = Ng - F*Ng ----
    if (t < 320)      gemm40x<GM_PLAIN>(mG, mF, mNg /*unused-safe*/, 0, t), // see below
                      gemm40x<GM_PLAIN>(mG, mF, mF, 0, t);
    else if (t < 640) gemm40x<GM_DNEG >(mD, mF, mNg, 0, t - 320);
    __syncthreads();

    // ---- P2: R = G*D  ||  e = (I(x)G) v ----
    if (t < 320) {
        gemm40x<GM_PLAIN>(mR, mG, mD, 0, t);
    } else {
        int el = t - 320;                                  // 0..479
        {
            int gg = el / PARAM, pp = el % PARAM;
            sE[el] = rowdot40(&mG[pp * MST], &sV[gg * PARAM]);
        }
        if (el < 320) {
            int e2 = el + 480;
            int gg = e2 / PARAM, pp = e2 % PARAM;
            sE[e2] = rowdot40(&mG[pp * MST], &sV[gg * PARAM]);
        }
    }
    __syncthreads();

    // ---- P3: C = 0.5(D + R + G*R)  ||  f = (I(x)G)e, u = v+e+f -> sT ----
    if (t < 320) {
        gemm40x<GM_CFIN>(mC, mG, mR, mD, t);
    } else {
        int el = t - 320;
        {
            int gg = el / PARAM, pp = el % PARAM;
            float f = rowdot40(&mG[pp * MST], &sE[gg * PARAM]);
            sT[el] = sV[el] + sE[el] + f;
        }
        if (el < 320) {
            int e2 = el + 480;
            int gg = e2 / PARAM, pp = e2 % PARAM;
            float f = rowdot40(&mG[pp * MST], &sE[gg * PARAM]);
            sT[e2] = sV[e2] + sE[e2] + f;
        }
    }
    __syncthreads();

    // ---- P4: b = 0.5*(u - (I(x)F)u); x0 = b; load C row into registers ----
    float b = 0.5f * (sT[t] - rowdot40(&mF[p * MST], &sT[g * PARAM]));
    float4 creg[10];
    #pragma unroll
    for (int i = 0; i < 10; ++i)
        creg[i] = *(const float4*)&mC[p * MST + 4 * i];
    __syncthreads();                 // sT (u) consumed before reuse as scratch
    sx[t] = b;
    __syncthreads();

    const float*  Mrow = &sM[g * GS];
    const float4* xrow = (const float4*)&sx[g * PARAM];

    // ---- Richardson sweeps: x <- b - (M (x) C) x ----
    #pragma unroll 1
    for (int it = 0; it < NITER; ++it) {
        // Phase A: T[g,p] = sum_q C[p,q] x[g,q]
        float tv = 0.f;
        #pragma unroll
        for (int i = 0; i < 10; ++i) {
            float4 c  = creg[i];
            float4 x4 = xrow[i];        // broadcast within g-group
            tv = fmaf(c.x, x4.x, tv);
            tv = fmaf(c.y, x4.y, tv);
            tv = fmaf(c.z, x4.z, tv);
            tv = fmaf(c.w, x4.w, tv);
        }
        sT[t] = tv;
        __syncthreads();

        // Phase B: x[g,p] = b - sum_g2 M[g,g2] T[g2,p]
        float acc = b;
        #pragma unroll
        for (int g2 = 0; g2 < GS; ++g2)
            acc = fmaf(-Mrow[g2], sT[g2 * PARAM + p], acc);  // M bcast, T conflict-free

        if (it == NITER - 1) {
            acc = fminf(fmaxf(acc, -1.0f), 1.0f);   // advrelu == clip
            out[sys * NN + t] = acc;
        } else {
            __syncthreads();
            sx[t] = acc;
            __syncthreads();
        }
    }
}

extern "C" void kernel_launch(void* const* d_in, const int* in_sizes, int n_in,
                              void* d_out, int out_size)
{
    const float* mat        = (const float*)d_in[0];
    const float* val        = (const float*)d_in[1];
    const float* selfintact = (const float*)d_in[2];
    const float* neigintact = (const float*)d_in[3];
    float* out = (float*)d_out;

    gliam_fused_kernel<<<NSYS, NN>>>(mat, val, selfintact, neigintact, out);
}

// round 13
// speedup vs baseline: 1.2407x; 1.2407x over previous
#include <cuda_runtime.h>

#define GS      20
#define PARAM   40
#define NN      (GS * PARAM)     // 800
#define NSYS    80               // B*A
#define MST     44               // padded matrix stride
#define NITER   3                // sweeps (verified R11: rel_err 1.52e-5, bias-dominated)

// ---------------------------------------------------------------------------
// One CTA per system, 800 threads.
// P = I(x)S + M(x)Ng,  F = S/2 - I.  Bpre = 0.5(I-F)(I+F^2+F^4): BS = I-F^6
// (bias 1.5e-5, measured).  x = b - (M(x)C)x,  C=Bpre*Ng, b=(I(x)Bpre)v.
// 3 Richardson sweeps.  Prep GEMMs: warp-cooperative tiling (R10, proven).
// ---------------------------------------------------------------------------

#define GM_PLAIN 0   // D = A*Bm
#define GM_H     1   // D = A*Bm + A + I      (H = G^2 + G + I, A=B=G)
#define GM_BF    2   // D = 0.5*(Bm - A*Bm)   (B = 0.5*(H - F*H))

// Warp-cooperative 40x40 GEMM, 10 warps (t < 320).
// Warp w: rows 4w..4w+3.  lane -> rr = lane>>3 (row), cc = lane&7.
// Cols per thread: {2cc,2cc+1}, {2cc+16,2cc+17}, and {2cc+32,2cc+33} if cc<8/2.
template <int MODE>
__device__ __forceinline__ void gemm40w(float* __restrict__ D,
                                        const float* __restrict__ A,
                                        const float* __restrict__ B,
                                        int t)
{
    if (t >= 320) return;
    const int lane = t & 31;
    const int rr   = lane >> 3;          // 0..3
    const int cc   = lane & 7;           // 0..7
    const int r    = 4 * (t >> 5) + rr;  // 0..39
    const int c0   = 2 * cc;             // 0..15
    const int c1   = c0 + 16;            // 16..31
    const int c2   = c0 + 32;            // 32..39 (cc<4 only)
    const bool has2 = (cc < 4);

    float a00 = 0.f, a01 = 0.f, a10 = 0.f, a11 = 0.f, a20 = 0.f, a21 = 0.f;
    const float4* Arow = (const float4*)(A + r * MST);
    #pragma unroll
    for (int k4 = 0; k4 < 10; ++k4) {
        float4 a4 = Arow[k4];
        #pragma unroll
        for (int j = 0; j < 4; ++j) {
            float av = (j == 0) ? a4.x : (j == 1) ? a4.y : (j == 2) ? a4.z : a4.w;
            const float* Bk = B + (4 * k4 + j) * MST;
            float2 b0 = *(const float2*)(Bk + c0);
            float2 b1 = *(const float2*)(Bk + c1);
            a00 = fmaf(av, b0.x, a00);  a01 = fmaf(av, b0.y, a01);
            a10 = fmaf(av, b1.x, a10);  a11 = fmaf(av, b1.y, a11);
            if (has2) {
                float2 b2 = *(const float2*)(Bk + c2);
                a20 = fmaf(av, b2.x, a20);  a21 = fmaf(av, b2.y, a21);
            }
        }
    }

    #pragma unroll
    for (int s = 0; s < 3; ++s) {
        if (s == 2 && !has2) break;
        int  c  = (s == 0) ? c0 : (s == 1) ? c1 : c2;
        float v0 = (s == 0) ? a00 : (s == 1) ? a10 : a20;
        float v1 = (s == 0) ? a01 : (s == 1) ? a11 : a21;
        float2 o;
        if (MODE == GM_H) {
            o.x = v0 + A[r * MST + c]     + (r == c     ? 1.0f : 0.0f);
            o.y = v1 + A[r * MST + c + 1] + (r == c + 1 ? 1.0f : 0.0f);
        } else if (MODE == GM_BF) {
            o.x = 0.5f * (B[r * MST + c]     - v0);
            o.y = 0.5f * (B[r * MST + c + 1] - v1);
        } else {
            o.x = v0; o.y = v1;
        }
        *(float2*)(D + r * MST + c) = o;
    }
}

// dot(Mat[p,:], vec[g,:]) with float4 reads
__device__ __forceinline__ float rowdot40(const float* __restrict__ Mrow,
                                          const float* __restrict__ vrow)
{
    const float4* m4 = (const float4*)Mrow;
    const float4* v4 = (const float4*)vrow;
    float acc = 0.f;
    #pragma unroll
    for (int i = 0; i < 10; ++i) {
        float4 m = m4[i], v = v4[i];
        acc = fmaf(m.x, v.x, acc);
        acc = fmaf(m.y, v.y, acc);
        acc = fmaf(m.z, v.z, acc);
        acc = fmaf(m.w, v.w, acc);
    }
    return acc;
}

__global__ __launch_bounds__(NN, 1)
void gliam_fused_kernel(const float* __restrict__ mat,        // (80,20,20)
                        const float* __restrict__ val,        // (80,800)
                        const float* __restrict__ selfintact, // (40,40)
                        const float* __restrict__ neigintact, // (40,40)
                        float* __restrict__ out)              // (80,800)
{
    __shared__ __align__(16) float mF [PARAM * MST];  // F = S/2 - I
    __shared__ __align__(16) float mG [PARAM * MST];  // G = F^2
    __shared__ __align__(16) float mH [PARAM * MST];  // H = I + G + G^2
    __shared__ __align__(16) float mB [PARAM * MST];  // Bpre
    __shared__ __align__(16) float mNg[PARAM * MST];  // Ng
    __shared__ __align__(16) float mC [PARAM * MST];  // C = Bpre*Ng
    __shared__ __align__(16) float sx [NN];           // iterate
    __shared__ __align__(16) float sT [NN];           // T scratch
    __shared__ __align__(16) float sV [NN];           // v
    __shared__ __align__(16) float sM [GS * GS];      // M

    const int sys = blockIdx.x;
    const int t   = threadIdx.x;     // 0..799
    const int g   = t / PARAM;       // 0..19
    const int p   = t % PARAM;       // 0..39

    // ---- stage inputs ----
    {
        int i0 = t, i1 = t + NN;
        int r0 = i0 / PARAM, c0 = i0 % PARAM;
        int r1 = i1 / PARAM, c1 = i1 % PARAM;
        mF [r0 * MST + c0] = 0.5f * selfintact[i0] - (r0 == c0 ? 1.0f : 0.0f);
        mF [r1 * MST + c1] = 0.5f * selfintact[i1] - (r1 == c1 ? 1.0f : 0.0f);
        mNg[r0 * MST + c0] = neigintact[i0];
        mNg[r1 * MST + c1] = neigintact[i1];
        sV[t] = val[sys * NN + t];
        if (t < GS * GS) sM[t] = mat[sys * GS * GS + t];
    }
    __syncthreads();

    // ---- prep: 4 warp-cooperative GEMMs ----
    gemm40w<GM_PLAIN>(mG, mF, mF, t);   __syncthreads();  // G = F^2
    gemm40w<GM_H    >(mH, mG, mG, t);   __syncthreads();  // H = I + G + G^2
    gemm40w<GM_BF   >(mB, mF, mH, t);   __syncthreads();  // Bpre = 0.5(H - F*H)
    gemm40w<GM_PLAIN>(mC, mB, mNg, t);                    // C = Bpre*Ng
    // b = (I(x)Bpre) v for this element (mB ready above; all 800 threads).
    // sx is untouched so far -> write b without a pre-barrier.
    float b = rowdot40(&mB[p * MST], &sV[g * PARAM]);
    sx[t] = b;                        // x0 = b
    __syncthreads();                  // mC stores + sx visible

    // ---- C[p,:] into registers ----
    float4 creg[10];
    #pragma unroll
    for (int i = 0; i < 10; ++i)
        creg[i] = *(const float4*)&mC[p * MST + 4 * i];

    const float*  Mrow = &sM[g * GS];
    const float4* xrow = (const float4*)&sx[g * PARAM];

    // ---- Richardson sweeps: x <- b - (M (x) C) x  (2 barriers/sweep) ----
    #pragma unroll 1
    for (int it = 0; it < NITER; ++it) {
        // Phase A: T[g,p] = sum_q C[p,q] x[g,q]
        float tv = 0.f;
        #pragma unroll
        for (int i = 0; i < 10; ++i) {
            float4 c  = creg[i];
            float4 x4 = xrow[i];        // broadcast within g-group
            tv = fmaf(c.x, x4.x, tv);
            tv = fmaf(c.y, x4.y, tv);
            tv = fmaf(c.z, x4.z, tv);
            tv = fmaf(c.w, x4.w, tv);
        }
        sT[t] = tv;
        __syncthreads();                // all phase-A sx reads + sT writes done

        // Phase B: x[g,p] = b - sum_g2 M[g,g2] T[g2,p]
        float acc = b;
        #pragma unroll
        for (int g2 = 0; g2 < GS; ++g2)
            acc = fmaf(-Mrow[g2], sT[g2 * PARAM + p], acc);  // M bcast, T conflict-free

        if (it == NITER - 1) {
            acc = fminf(fmaxf(acc, -1.0f), 1.0f);   // advrelu == clip
            out[sys * NN + t] = acc;
        } else {
            // sx writes are safe NOW: every thread's phase-A sx reads completed
            // before the barrier above (sx and sT are disjoint buffers).
            sx[t] = acc;
            __syncthreads();            // covers sx visibility + sT reuse next sweep
        }
    }
}

extern "C" void kernel_launch(void* const* d_in, const int* in_sizes, int n_in,
                              void* d_out, int out_size)
{
    const float* mat        = (const float*)d_in[0];
    const float* val        = (const float*)d_in[1];
    const float* selfintact = (const float*)d_in[2];
    const float* neigintact = (const float*)d_in[3];
    float* out = (float*)d_out;

    gliam_fused_kernel<<<NSYS, NN>>>(mat, val, selfintact, neigintact, out);
}